// round 14
// baseline (speedup 1.0000x reference)
#include <cuda_runtime.h>
#include <cuda.h>
#include <cstdint>

// Problem constants (reference: D=48, K=12, S=4, BS=8)
#define D_   48
#define N_   (D_ * D_)      // 2304
#define K_   12
#define KK_  (K_ * K_)      // 144
#define NW1_ 10
#define NW_  (NW1_ * NW1_)  // 100
#define BS_  8

#define TROWS 48
#define TCOLS 192
#define TILE_BYTES (TROWS * TCOLS * 4)   // 36864

// Tile keyed by SOURCE coords (b, pr, qrg): rows pr*48..+48, cols qrg*192..+192
// of x[b], loaded ONCE chip-wide via TMA; serves all output chunks
// (wr = qrg - jB, ia = pr - 4wr). Phase-2 stores are PLAIN write-back
// (evict-normal): across graph replays the 66MB output stays dirty-resident
// in L2 and is re-dirtied without draining — removing the DRAM write stream
// that has been the ~19.8us floor in every prior design.

__global__ void __launch_bounds__(288) subm_tma_dedup_wb(
    const __grid_constant__ CUtensorMap tmap, float* __restrict__ out)
{
    __shared__ alignas(128) float T[TROWS * TCOLS];
    __shared__ alignas(8) unsigned long long mbar;

    int bi   = blockIdx.x;          // = (b*48 + pr)*12 + qrg
    int qrg  = bi % 12;
    int pr   = (bi / 12) % 48;
    int b    = bi / (12 * 48);

    // validity: 4wr <= pr <= 4wr+11  AND  qrg-2 <= wr <= qrg, 0<=wr<=9
    int wmin_row = pr - 11; wmin_row = wmin_row < 0 ? 0 : ((wmin_row + 3) >> 2);
    int wmax_row = pr >> 2; if (wmax_row > 9) wmax_row = 9;
    int wlo = qrg - 2; if (wlo < wmin_row) wlo = wmin_row; if (wlo < 0) wlo = 0;
    int whi = qrg;     if (whi > wmax_row) whi = wmax_row;
    if (wlo > whi) return;          // invalid tile, early exit

    uint32_t s_tile, s_mbar;
    asm("{ .reg .u64 t; cvta.to.shared.u64 t, %1; cvt.u32.u64 %0, t; }"
        : "=r"(s_tile) : "l"(T));
    asm("{ .reg .u64 t; cvta.to.shared.u64 t, %1; cvt.u32.u64 %0, t; }"
        : "=r"(s_mbar) : "l"(&mbar));

    if (threadIdx.x == 0) {
        asm volatile("mbarrier.init.shared.b64 [%0], 1;" :: "r"(s_mbar) : "memory");
        asm volatile("fence.proxy.async.shared::cta;" ::: "memory");
    }
    __syncthreads();

    if (threadIdx.x == 0) {
        asm volatile("mbarrier.arrive.expect_tx.shared.b64 _, [%0], %1;"
                     :: "r"(s_mbar), "r"((uint32_t)TILE_BYTES) : "memory");
        int c0 = qrg * TCOLS;
        int r0 = pr * D_;
        asm volatile(
            "cp.async.bulk.tensor.3d.shared::cta.global.tile.mbarrier::complete_tx::bytes "
            "[%0], [%1, {%2, %3, %4}], [%5];"
            :: "r"(s_tile), "l"(&tmap), "r"(c0), "r"(r0), "r"(b), "r"(s_mbar)
            : "memory");
    }

    // All threads wait for TMA completion (phase 0).
    asm volatile(
        "{\n\t.reg .pred P1;\n\t"
        "LW%=:\n\t"
        "mbarrier.try_wait.parity.shared.b64 P1, [%0], 0;\n\t"
        "@P1 bra LD%=;\n\t"
        "bra LW%=;\n\t"
        "LD%=:\n\t}"
        :: "r"(s_mbar) : "memory");

    // Phase 2: per-thread fixed (qj, ib, wcp); iterate wc (5 iters) per chunk.
    int tid  = threadIdx.x;
    int m    = tid % 144;
    int wcp  = tid / 144;           // 0 or 1
    int qj   = m % K_;
    int ib   = m / K_;
    int jaLoc = qj / 3;
    int sub   = qj % 3;

    int sidx0 = ib * TCOLS + jaLoc * 48 + sub * 4 + wcp * 772;

    for (int wr = wlo; wr <= whi; wr++) {
        int ia = pr - 4 * wr;
        int jB = qrg - wr;

        size_t obase = ((((size_t)b * NW_ + wr * NW1_) * KK_) + ia * K_ + ib) * KK_
                     + jB * 48 + qj * 4 + (size_t)wcp * (KK_ * KK_);
        int sidx = sidx0;
#pragma unroll
        for (int it = 0; it < 5; it++) {
            float4 v = *reinterpret_cast<const float4*>(&T[sidx]);
            *reinterpret_cast<float4*>(out + obase) = v;   // write-back, evict-normal
            sidx  += 2 * 772;
            obase += 2 * (size_t)(KK_ * KK_);
        }
    }
}

// ---------------- fallback (plain gather, best known LDG design) ----------
__global__ void __launch_bounds__(256) submanifold_gather_q12(
    const float* __restrict__ x, float* __restrict__ out)
{
    int t = blockIdx.x * 256 + threadIdx.x;
    int q    = t % 36;
    int rest = t / 36;
    int ia   = rest % K_;
    rest     = rest / K_;
    int w    = rest % NW_;
    int b    = rest / NW_;
    int wr = w / NW1_;
    int wc = w % NW1_;
    int ja  = q / 3;
    int sub = q % 3;
    int r0 = (wr * 4 + ia) * D_ + wc * 4;
    int c  = (wr * 4 + ja) * D_ + wc * 4 + sub * 4;
    const float4* src = reinterpret_cast<const float4*>(x + ((size_t)b * N_ + r0) * N_ + c);
    size_t dbase = (((size_t)(b * NW_ + w)) * KK_ + ia * K_) * 36 + q;
    float4* dst = reinterpret_cast<float4*>(out) + dbase;
#pragma unroll
    for (int ib = 0; ib < K_; ib++)
        dst[(size_t)ib * 36] = src[(size_t)ib * (N_ / 4)];
}

// ---------------------------------------------------------------------------

typedef CUresult (*PFN_tmapEncode)(
    CUtensorMap*, CUtensorMapDataType, cuuint32_t, void*,
    const cuuint64_t*, const cuuint64_t*, const cuuint32_t*, const cuuint32_t*,
    CUtensorMapInterleave, CUtensorMapSwizzle, CUtensorMapL2promotion,
    CUtensorMapFloatOOBfill);

extern "C" void kernel_launch(void* const* d_in, const int* in_sizes, int n_in,
                              void* d_out, int out_size)
{
    float* x   = (float*)d_in[0];
    float* out = (float*)d_out;

    PFN_tmapEncode encode = nullptr;
    cudaDriverEntryPointQueryResult qres;
    cudaGetDriverEntryPoint("cuTensorMapEncodeTiled", (void**)&encode,
                            cudaEnableDefault, &qres);

    bool tma_ok = false;
    CUtensorMap tmap;
    if (encode && qres == cudaDriverEntryPointSuccess) {
        // 3D view of x: [col (2304 floats, inner), row (2304), b (8)]
        cuuint64_t dims[3]    = {(cuuint64_t)N_, (cuuint64_t)N_, (cuuint64_t)BS_};
        cuuint64_t strides[2] = {
            (cuuint64_t)N_ * 4,
            (cuuint64_t)N_ * N_ * 4
        };
        cuuint32_t box[3]  = {TCOLS, TROWS, 1};   // 192 x 48 x 1 (768B rows)
        cuuint32_t estr[3] = {1, 1, 1};
        CUresult r = encode(&tmap, CU_TENSOR_MAP_DATA_TYPE_FLOAT32, 3, (void*)x,
                            dims, strides, box, estr,
                            CU_TENSOR_MAP_INTERLEAVE_NONE,
                            CU_TENSOR_MAP_SWIZZLE_NONE,
                            CU_TENSOR_MAP_L2_PROMOTION_L2_128B,
                            CU_TENSOR_MAP_FLOAT_OOB_FILL_NONE);
        tma_ok = (r == CUDA_SUCCESS);
    }

    if (tma_ok) {
        subm_tma_dedup_wb<<<BS_ * 48 * 12, 288>>>(tmap, out);   // 4608 CTAs
    } else {
        const int total_threads = BS_ * NW_ * K_ * 36;
        submanifold_gather_q12<<<total_threads / 256, 256>>>(x, out);
    }
}

// round 15
// speedup vs baseline: 1.1481x; 1.1481x over previous
#include <cuda_runtime.h>
#include <cuda.h>
#include <cstdint>

// Problem constants (reference: D=48, K=12, S=4, BS=8)
#define D_   48
#define N_   (D_ * D_)      // 2304
#define K_   12
#define KK_  (K_ * K_)      // 144
#define NW1_ 10
#define NW_  (NW1_ * NW1_)  // 100
#define BS_  8

#define TROWS 48
#define TCOLS 192
#define TILE_BYTES (TROWS * TCOLS * 4)   // 36864

// Tile keyed by SOURCE coords (b, pr, qrg): rows pr*48..+48, cols qrg*192..+192
// of x[b]; loaded ONCE chip-wide via one dense TMA (768B rows); serves all
// output chunks (wr = qrg - jB, ia = pr - 4wr).
// Steady state (measured over R5..R14): reads are L2-resident, DRAM carries
// ~66MB of output drain + ~7MB read misses at the mixed-stream rate -> ~19.5us
// floor. This round minimizes SM-side contention around that floor:
//   - mbarrier wait uses the SUSPENDED try_wait form (sleep, not spin), so
//     waiting warps free issue slots for other CTAs' store phases
//   - stores remain __stcs (evict-first beat write-back on wall time).

__global__ void __launch_bounds__(288) subm_tma_dedup_v2(
    const __grid_constant__ CUtensorMap tmap, float* __restrict__ out)
{
    __shared__ alignas(128) float T[TROWS * TCOLS];
    __shared__ alignas(8) unsigned long long mbar;

    int bi   = blockIdx.x;          // = (b*48 + pr)*12 + qrg
    int qrg  = bi % 12;
    int pr   = (bi / 12) % 48;
    int b    = bi / (12 * 48);

    // validity: 4wr <= pr <= 4wr+11  AND  qrg-2 <= wr <= qrg, 0<=wr<=9
    int wmin_row = pr - 11; wmin_row = wmin_row < 0 ? 0 : ((wmin_row + 3) >> 2);
    int wmax_row = pr >> 2; if (wmax_row > 9) wmax_row = 9;
    int wlo = qrg - 2; if (wlo < wmin_row) wlo = wmin_row; if (wlo < 0) wlo = 0;
    int whi = qrg;     if (whi > wmax_row) whi = wmax_row;
    if (wlo > whi) return;          // invalid tile, early exit

    uint32_t s_tile, s_mbar;
    asm("{ .reg .u64 t; cvta.to.shared.u64 t, %1; cvt.u32.u64 %0, t; }"
        : "=r"(s_tile) : "l"(T));
    asm("{ .reg .u64 t; cvta.to.shared.u64 t, %1; cvt.u32.u64 %0, t; }"
        : "=r"(s_mbar) : "l"(&mbar));

    if (threadIdx.x == 0) {
        asm volatile("mbarrier.init.shared.b64 [%0], 1;" :: "r"(s_mbar) : "memory");
        asm volatile("fence.proxy.async.shared::cta;" ::: "memory");
    }
    __syncthreads();

    if (threadIdx.x == 0) {
        asm volatile("mbarrier.arrive.expect_tx.shared.b64 _, [%0], %1;"
                     :: "r"(s_mbar), "r"((uint32_t)TILE_BYTES) : "memory");
        int c0 = qrg * TCOLS;
        int r0 = pr * D_;
        asm volatile(
            "cp.async.bulk.tensor.3d.shared::cta.global.tile.mbarrier::complete_tx::bytes "
            "[%0], [%1, {%2, %3, %4}], [%5];"
            :: "r"(s_tile), "l"(&tmap), "r"(c0), "r"(r0), "r"(b), "r"(s_mbar)
            : "memory");
    }

    // Phase-2 per-thread constants (computed while TMA is in flight).
    int tid  = threadIdx.x;
    int m    = tid % 144;
    int wcp  = tid / 144;           // 0 or 1
    int qj   = m % K_;
    int ib   = m / K_;
    int jaLoc = qj / 3;
    int sub   = qj % 3;
    int sidx0 = ib * TCOLS + jaLoc * 48 + sub * 4 + wcp * 772;

    // Suspended wait for TMA completion (phase 0): try_wait with sleep hint,
    // warps park instead of spinning.
    {
        uint32_t done;
        asm volatile(
            "{\n\t.reg .pred p;\n\t"
            "mbarrier.try_wait.parity.shared.b64 p, [%1], 0, 0x989680;\n\t"
            "selp.b32 %0, 1, 0, p;\n\t}"
            : "=r"(done) : "r"(s_mbar) : "memory");
        if (!done) {
            asm volatile(
                "{\n\t.reg .pred P1;\n\t"
                "LW%=:\n\t"
                "mbarrier.try_wait.parity.shared.b64 P1, [%0], 0, 0x989680;\n\t"
                "@P1 bra LD%=;\n\t"
                "bra LW%=;\n\t"
                "LD%=:\n\t}"
                :: "r"(s_mbar) : "memory");
        }
    }

    for (int wr = wlo; wr <= whi; wr++) {
        int ia = pr - 4 * wr;
        int jB = qrg - wr;

        size_t obase = ((((size_t)b * NW_ + wr * NW1_) * KK_) + ia * K_ + ib) * KK_
                     + jB * 48 + qj * 4 + (size_t)wcp * (KK_ * KK_);
        int sidx = sidx0;
#pragma unroll
        for (int it = 0; it < 5; it++) {
            float4 v = *reinterpret_cast<const float4*>(&T[sidx]);
            __stcs(reinterpret_cast<float4*>(out + obase), v);
            sidx  += 2 * 772;
            obase += 2 * (size_t)(KK_ * KK_);
        }
    }
}

// ---------------- fallback (plain gather, best known LDG design) ----------
__global__ void __launch_bounds__(256) submanifold_gather_q12(
    const float* __restrict__ x, float* __restrict__ out)
{
    int t = blockIdx.x * 256 + threadIdx.x;
    int q    = t % 36;
    int rest = t / 36;
    int ia   = rest % K_;
    rest     = rest / K_;
    int w    = rest % NW_;
    int b    = rest / NW_;
    int wr = w / NW1_;
    int wc = w % NW1_;
    int ja  = q / 3;
    int sub = q % 3;
    int r0 = (wr * 4 + ia) * D_ + wc * 4;
    int c  = (wr * 4 + ja) * D_ + wc * 4 + sub * 4;
    const float4* src = reinterpret_cast<const float4*>(x + ((size_t)b * N_ + r0) * N_ + c);
    size_t dbase = (((size_t)(b * NW_ + w)) * KK_ + ia * K_) * 36 + q;
    float4* dst = reinterpret_cast<float4*>(out) + dbase;
#pragma unroll
    for (int ib = 0; ib < K_; ib++)
        dst[(size_t)ib * 36] = src[(size_t)ib * (N_ / 4)];
}

// ---------------------------------------------------------------------------

typedef CUresult (*PFN_tmapEncode)(
    CUtensorMap*, CUtensorMapDataType, cuuint32_t, void*,
    const cuuint64_t*, const cuuint64_t*, const cuuint32_t*, const cuuint32_t*,
    CUtensorMapInterleave, CUtensorMapSwizzle, CUtensorMapL2promotion,
    CUtensorMapFloatOOBfill);

extern "C" void kernel_launch(void* const* d_in, const int* in_sizes, int n_in,
                              void* d_out, int out_size)
{
    float* x   = (float*)d_in[0];
    float* out = (float*)d_out;

    PFN_tmapEncode encode = nullptr;
    cudaDriverEntryPointQueryResult qres;
    cudaGetDriverEntryPoint("cuTensorMapEncodeTiled", (void**)&encode,
                            cudaEnableDefault, &qres);

    bool tma_ok = false;
    CUtensorMap tmap;
    if (encode && qres == cudaDriverEntryPointSuccess) {
        // 3D view of x: [col (2304 floats, inner), row (2304), b (8)]
        cuuint64_t dims[3]    = {(cuuint64_t)N_, (cuuint64_t)N_, (cuuint64_t)BS_};
        cuuint64_t strides[2] = {
            (cuuint64_t)N_ * 4,
            (cuuint64_t)N_ * N_ * 4
        };
        cuuint32_t box[3]  = {TCOLS, TROWS, 1};   // 192 x 48 x 1 (768B rows)
        cuuint32_t estr[3] = {1, 1, 1};
        CUresult r = encode(&tmap, CU_TENSOR_MAP_DATA_TYPE_FLOAT32, 3, (void*)x,
                            dims, strides, box, estr,
                            CU_TENSOR_MAP_INTERLEAVE_NONE,
                            CU_TENSOR_MAP_SWIZZLE_NONE,
                            CU_TENSOR_MAP_L2_PROMOTION_L2_128B,
                            CU_TENSOR_MAP_FLOAT_OOB_FILL_NONE);
        tma_ok = (r == CUDA_SUCCESS);
    }

    if (tma_ok) {
        subm_tma_dedup_v2<<<BS_ * 48 * 12, 288>>>(tmap, out);   // 4608 CTAs
    } else {
        const int total_threads = BS_ * NW_ * K_ * 36;
        submanifold_gather_q12<<<total_threads / 256, 256>>>(x, out);
    }
}